// round 2
// baseline (speedup 1.0000x reference)
#include <cuda_runtime.h>
#include <math.h>

#define DD 96
#define NPART 48

// Scratch (no allocations allowed): G matrix (fp64) and per-particle probs.
__device__ double g_G[DD * DD];
__device__ double g_pk[NPART];

// ---------------------------------------------------------------------------
// Kernel 1: G = I - P P^T   (96x96, internal fp64, input fp32).
// grid=96 blocks, 96 threads. Block i computes row i.
// ---------------------------------------------------------------------------
__global__ void build_G_kernel(const float* __restrict__ P) {
    __shared__ double Pt[NPART][DD];  // transposed: Pt[t][i] = P[i][t]
    const int i = blockIdx.x;
    const int tid = threadIdx.x;  // 96 threads

    for (int idx = tid; idx < DD * NPART; idx += DD) {
        int r = idx / NPART;
        int t = idx - r * NPART;
        Pt[t][r] = (double)P[idx];
    }
    __syncthreads();

    const int j = tid;
    double dot = 0.0;
#pragma unroll
    for (int t = 0; t < NPART; t++) {
        dot = fma(Pt[t][i], Pt[t][j], dot);  // broadcast + conflict-free
    }
    g_G[i * DD + j] = ((i == j) ? 1.0 : 0.0) - dot;
}

// ---------------------------------------------------------------------------
// Kernel 2: per-k unpivoted LU of the leading m x m block of M_k = G - diag(n<k),
// m = 49 + k.  Leading principal minors d_j = prod of pivots, so
//   probs[k,x] = -(prod_{t=xmin}^{x-1} piv_t) * (piv_x - 1),  x in [xmin, m)
// grid = 48 blocks (one per particle k), 256 threads each.
// Dynamic shared: A[96][97] doubles (74496 B).
// ---------------------------------------------------------------------------
__global__ void lu_probs_kernel(const int* __restrict__ occ,
                                float* __restrict__ out) {
    extern __shared__ double A_[];          // [DD][DD+1], pitch 97
    __shared__ double piv[DD];
    __shared__ double lcol[DD];
    __shared__ double sc[2][DD];
    __shared__ double s_inv;
    __shared__ int s_occ[NPART];

    const int k = blockIdx.x;
    const int m = DD - NPART + k + 1;       // xmax = 49 + k
    const int tid = threadIdx.x;            // 256
    const int tx = tid & 31;
    const int ty = tid >> 5;                // (32, 8)
    const int pitch = DD + 1;

    if (tid < NPART) s_occ[tid] = occ[tid];

    // Load leading m x m block of G
    for (int r = ty; r < m; r += 8)
        for (int c = tx; c < m; c += 32)
            A_[r * pitch + c] = g_G[r * DD + c];
    __syncthreads();

    // Subtract occupancy of particles < k on the diagonal (distinct positions)
    if (tid < k) {
        int p = s_occ[tid];
        if (p < m) A_[p * pitch + p] -= 1.0;
    }

    // Unpivoted right-looking LU on the leading m x m block
    for (int i = 0; i < m - 1; i++) {
        __syncthreads();                     // previous trailing update done
        if (tid == 0) {
            double pv = A_[i * pitch + i];
            piv[i] = pv;
            s_inv = 1.0 / pv;
        }
        __syncthreads();
        {
            double inv = s_inv;
            for (int r = i + 1 + tid; r < m; r += 256)
                lcol[r] = A_[r * pitch + i] * inv;
        }
        __syncthreads();
        for (int r = i + 1 + ty; r < m; r += 8) {
            double lr = lcol[r];
            const double* __restrict__ urow = &A_[i * pitch];
            double* __restrict__ arow = &A_[r * pitch];
            for (int c = i + 1 + tx; c < m; c += 32)
                arow[c] = fma(-lr, urow[c], arow[c]);
        }
    }
    __syncthreads();
    if (tid == 0) piv[m - 1] = A_[(m - 1) * pitch + (m - 1)];
    __syncthreads();

    const int xmin = (k == 0) ? 0 : s_occ[k - 1] + 1;

    // Inclusive prefix product of pivots masked to [xmin, m)
    if (tid < DD) {
        int x = tid;
        sc[0][x] = (x >= xmin && x < m) ? piv[x] : 1.0;
    }
    __syncthreads();
    int src = 0;
    for (int off = 1; off < DD; off <<= 1) {
        if (tid < DD) {
            double v = sc[src][tid];
            if (tid >= off) v *= sc[src][tid - off];
            sc[src ^ 1][tid] = v;
        }
        __syncthreads();
        src ^= 1;
    }

    if (tid < DD) {
        int x = tid;
        double pr = 0.0;
        if (x >= xmin && x < m) {
            double S = (x == xmin) ? 1.0 : sc[src][x - 1];
            pr = -S * (piv[x] - 1.0);
            if (!(fabs(pr) > 1e-15)) pr = 0.0;
        }
        out[k * DD + x] = (float)pr;
        if (x == s_occ[k]) g_pk[k] = pr;
    }
}

// ---------------------------------------------------------------------------
// Kernel 3: prob_sample = prod_k p_k.  One warp, butterfly multiply-reduce.
// ---------------------------------------------------------------------------
__global__ void prod_kernel(float* __restrict__ out) {
    const int t = threadIdx.x;  // 32
    double v = g_pk[t];
    if (t < 16) v *= g_pk[32 + t];
#pragma unroll
    for (int off = 16; off > 0; off >>= 1)
        v *= __shfl_xor_sync(0xFFFFFFFFu, v, off);
    if (t == 0) out[NPART * DD] = (float)v;
}

extern "C" void kernel_launch(void* const* d_in, const int* in_sizes, int n_in,
                              void* d_out, int out_size) {
    // Identify inputs by element count: P has 96*48=4608, occ has 48.
    const float* P;
    const int* occ;
    if (in_sizes[0] == DD * NPART) {
        P = (const float*)d_in[0];
        occ = (const int*)d_in[1];
    } else {
        P = (const float*)d_in[1];
        occ = (const int*)d_in[0];
    }
    float* out = (float*)d_out;

    const int smem = DD * (DD + 1) * (int)sizeof(double);  // 74496 B
    cudaFuncSetAttribute(lu_probs_kernel,
                         cudaFuncAttributeMaxDynamicSharedMemorySize, smem);

    build_G_kernel<<<DD, DD>>>(P);
    lu_probs_kernel<<<NPART, 256, smem>>>(occ, out);
    prod_kernel<<<1, 32>>>(out);
}